// round 13
// baseline (speedup 1.0000x reference)
#include <cuda_runtime.h>
#include <math.h>

#define Bc 2
#define Sc 2048
#define Dc 1024
#define Hc 16
#define DKc 64
#define BSc (Bc*Sc)   // 4096

// Scratch (no allocations allowed)
__device__ float g_qkv[(size_t)BSc * 3 * Dc];      // [B,S,3,H,DK]
__device__ float g_attn[(size_t)BSc * Dc];         // [B,S,D]
__device__ float g_ctab[Sc * 32];                  // RoPE cos table
__device__ float g_stab[Sc * 32];                  // RoPE sin table

// Packed tf32 tile buffers for the GEMMs (tile-major, fragment order)
__device__ uint2 g_apk_x[(size_t)BSc * Dc / 2];
__device__ uint2 g_bpk_qkv[(size_t)Dc * 3 * Dc / 2];
__device__ uint2 g_apk_attn[(size_t)BSc * Dc / 2];
__device__ uint2 g_bpk_wo[(size_t)Dc * Dc / 2];

// Packed tf32 Q/K/V for flash (written by rope_pack)
__device__ uint2 g_qpk[(size_t)32 * 16 * 4096];    // [bh][qt128] a-frag pairs
__device__ uint2 g_kpk[(size_t)32 * 32 * 2048];    // [bh][kt64]  b-frag pairs
__device__ uint2 g_vpk[(size_t)32 * 32 * 2048];    // [bh][kt64]  b-frag pairs

__device__ __forceinline__ unsigned f2tf(float x) {
    unsigned r;
    asm("cvt.rna.tf32.f32 %0, %1;" : "=r"(r) : "f"(x));
    return r;
}

__device__ __forceinline__ void mma8(float4& d, uint2 a01, uint2 a23, uint2 b) {
    asm volatile(
        "mma.sync.aligned.m16n8k8.row.col.f32.tf32.tf32.f32 "
        "{%0,%1,%2,%3}, {%4,%5,%6,%7}, {%8,%9}, {%0,%1,%2,%3};\n"
        : "+f"(d.x), "+f"(d.y), "+f"(d.z), "+f"(d.w)
        : "r"(a01.x), "r"(a01.y), "r"(a23.x), "r"(a23.y), "r"(b.x), "r"(b.y));
}

__device__ __forceinline__ void cpa16(unsigned dst, const void* src) {
    asm volatile("cp.async.cg.shared.global [%0], [%1], 16;"
                 :: "r"(dst), "l"(src));
}

// ---------------------------------------------------------------------------
// Pre-pack A[M,K=1024] -> tile-major a-fragment pairs (unchanged from R10)
// ---------------------------------------------------------------------------
__global__ void prepackA_kernel(const float* __restrict__ A,
                                uint2* __restrict__ out, int K) {
    int idx = blockIdx.x * blockDim.x + threadIdx.x;
    int k = idx & 31;
    int rg = (idx >> 5) & 63;
    int ck = idx >> 11;
    int kt = ck & 31;
    int mt = ck >> 5;
    int r = mt * 128 + ((rg >> 3) << 4) + (rg & 7);
    int col = kt * 32 + k;
    out[idx] = make_uint2(f2tf(A[(size_t)r * K + col]),
                          f2tf(A[(size_t)(r + 8) * K + col]));
}

// ---------------------------------------------------------------------------
// Pre-pack B[K=1024,N] -> tile-major b-fragment pairs (unchanged from R10)
// ---------------------------------------------------------------------------
__global__ void prepackB_kernel(const float* __restrict__ B,
                                uint2* __restrict__ out, int N) {
    int idx = blockIdx.x * blockDim.x + threadIdx.x;
    int pos = idx & 2047;
    int ck = idx >> 11;
    int kt = ck & 31;
    int nt = ck >> 5;
    int tg = pos & 3;
    int col = (((pos >> 5) & 15) << 3) + ((pos >> 2) & 7);
    int ks = pos >> 9;
    int row = kt * 32 + ks * 8 + tg;
    int c = nt * 128 + col;
    out[idx] = make_uint2(f2tf(B[(size_t)row * N + c]),
                          f2tf(B[(size_t)(row + 4) * N + c]));
}

// ---------------------------------------------------------------------------
// tf32 GEMM on prepacked tiles, cp.async double-buffered (unchanged from R10)
// ---------------------------------------------------------------------------
#define AS 36
#define BUFA_BYTES (64 * AS * 8)
#define BUFB_BYTES (64 * 32 * 8)
#define SMEM_TOTAL (2 * (BUFA_BYTES + BUFB_BYTES))   // 69632

__global__ __launch_bounds__(256, 2)
void tgemm_packed(const uint2* __restrict__ Apk,
                  const uint2* __restrict__ Bpk,
                  float* __restrict__ C, int M, int N) {
    extern __shared__ char smraw[];
    unsigned smem_u;
    asm("{ .reg .u64 t; cvta.to.shared.u64 t, %1; cvt.u32.u64 %0, t; }"
        : "=r"(smem_u) : "l"(smraw));
    const unsigned sA0 = smem_u;
    const unsigned sB0 = smem_u + 2 * BUFA_BYTES;

    const int tid = threadIdx.x;
    const int lane = tid & 31;
    const int w = tid >> 5;
    const int g = lane >> 2;
    const int tig = lane & 3;
    const int wm = w >> 2;
    const int wn = w & 3;
    const int mt_blk = blockIdx.y;
    const int nt_blk = blockIdx.x;

    const uint2* Abase = Apk + (size_t)mt_blk * 32 * 2048;
    const uint2* Bbase = Bpk + (size_t)nt_blk * 32 * 2048;

    auto issue = [&](int kt, int b) {
        const uint2* at = Abase + (size_t)kt * 2048;
        const uint2* bt = Bbase + (size_t)kt * 2048;
        unsigned dA = sA0 + b * BUFA_BYTES;
        unsigned dB = sB0 + b * BUFB_BYTES;
#pragma unroll
        for (int i = 0; i < 4; i++) {
            int e = tid + i * 256;
            int rg = e >> 4, c = e & 15;
            cpa16(dA + rg * (AS * 8) + c * 16, at + e * 2);
        }
#pragma unroll
        for (int i = 0; i < 4; i++) {
            int e = tid + i * 256;
            cpa16(dB + e * 16, bt + e * 2);
        }
        asm volatile("cp.async.commit_group;");
    };

    issue(0, 0);

    float4 acc[4][4];
#pragma unroll
    for (int i = 0; i < 4; i++)
#pragma unroll
        for (int j = 0; j < 4; j++) acc[i][j] = make_float4(0.f, 0.f, 0.f, 0.f);

    for (int kt = 0; kt < 32; kt++) {
        const int b = kt & 1;
        if (kt + 1 < 32) {
            issue(kt + 1, b ^ 1);
            asm volatile("cp.async.wait_group 1;");
        } else {
            asm volatile("cp.async.wait_group 0;");
        }
        __syncthreads();

        const uint2* Ap = (const uint2*)(smraw + (size_t)b * BUFA_BYTES);
        const uint2* Bp = (const uint2*)(smraw + 2 * BUFA_BYTES
                                               + (size_t)b * BUFB_BYTES);
#pragma unroll
        for (int ks = 0; ks < 4; ks++) {
            uint2 bfr[4];
#pragma unroll
            for (int nt = 0; nt < 4; nt++)
                bfr[nt] = Bp[(ks * 16 + wn * 4 + nt) * 32 + lane];
#pragma unroll
            for (int mt = 0; mt < 4; mt++) {
                uint2 a01 = Ap[(wm * 32 + mt * 8 + g) * AS + ks * 8 + tig];
                uint2 a23 = Ap[(wm * 32 + mt * 8 + g) * AS + ks * 8 + tig + 4];
#pragma unroll
                for (int nt = 0; nt < 4; nt++)
                    mma8(acc[mt][nt], a01, a23, bfr[nt]);
            }
        }
        __syncthreads();
    }

    const int m0 = mt_blk << 7;
    const int n0 = nt_blk << 7;
#pragma unroll
    for (int mt = 0; mt < 4; mt++) {
        int row = m0 + wm * 64 + mt * 16 + g;
#pragma unroll
        for (int nt = 0; nt < 4; nt++) {
            int col = n0 + wn * 32 + nt * 8 + 2 * tig;
            *(float2*)&C[(size_t)row * N + col] =
                make_float2(acc[mt][nt].x, acc[mt][nt].y);
            *(float2*)&C[(size_t)(row + 8) * N + col] =
                make_float2(acc[mt][nt].z, acc[mt][nt].w);
        }
    }
}

// ---------------------------------------------------------------------------
// RoPE table precompute (unchanged)
// ---------------------------------------------------------------------------
__global__ void rope_table_kernel() {
    int idx = blockIdx.x * blockDim.x + threadIdx.x;
    int d2 = idx & 31;
    int s = idx >> 5;
    float invf = 1.0f / powf(10000.0f, (float)d2 * (1.0f / 32.0f));
    float ang = (float)s * invf;
    float sn, c;
    sincosf(ang, &sn, &c);
    g_ctab[idx] = c;
    g_stab[idx] = sn;
}

// ---------------------------------------------------------------------------
// RoPE + pack: applies rotary, then writes Q/K/V directly in the tf32
// fragment-packed tile layouts flash consumes. Same arithmetic as before
// (fp32 rope -> [scale] -> cvt.rna.tf32), just relocated.
// ---------------------------------------------------------------------------
__global__ void rope_pack_kernel(const float* __restrict__ qkv,
                                 uint2* __restrict__ Qpk,
                                 uint2* __restrict__ Kpk,
                                 uint2* __restrict__ Vpk) {
    int idx = blockIdx.x * blockDim.x + threadIdx.x;  // [b][s][h][d]
    int d = idx & 63;
    int h = (idx >> 6) & (Hc - 1);
    int s = (idx >> 10) & (Sc - 1);
    int b = idx >> 21;

    const float* base = qkv + (size_t)(b * Sc + s) * 3 * Dc + h * DKc;
    float qv = base[d];
    float kv = base[Dc + d];
    float vv = base[2 * Dc + d];

    int d2 = d & 31;
    float c = g_ctab[s * 32 + d2];
    float sn = g_stab[s * 32 + d2];

    int dp = d ^ 32;
    float qp = base[dp];
    float kp = base[Dc + dp];
    float sgn = (d < 32) ? -1.0f : 1.0f;

    unsigned qo = f2tf((qv * c + sgn * qp * sn) * 0.125f);  // fold 1/sqrt(dk)
    unsigned ko = f2tf(kv * c + sgn * kp * sn);
    unsigned vo = f2tf(vv);

    const int bh = b * Hc + h;

    // Q: a-frag pairs, tile (bh, s>>7), pos rg*64+d, half = (r&15)>=8
    {
        int qt = s >> 7, r = s & 127;
        int grp = r >> 4, wi = r & 15;
        size_t basei = ((size_t)bh * 16 + qt) * 4096 + (grp * 8 + (wi & 7)) * 64 + d;
        ((unsigned*)Qpk)[basei * 2 + (wi >> 3)] = qo;
    }
    // K: b-frag pairs over d, tile (bh, s>>6)
    {
        int kt = s >> 6, key = s & 63;
        int ks = d >> 3, j = d & 7;
        size_t basei = ((size_t)bh * 32 + kt) * 2048
                     + (ks * 8 + (key >> 3)) * 32 + (key & 7) * 4 + (j & 3);
        ((unsigned*)Kpk)[basei * 2 + (j >> 2)] = ko;
    }
    // V: b-frag pairs over rows, tile (bh, s>>6)
    {
        int kt = s >> 6, rk = s & 63;
        int js = rk >> 3, tg = rk & 7;
        size_t basei = ((size_t)bh * 32 + kt) * 2048
                     + (js * 8 + (d >> 3)) * 32 + (d & 7) * 4 + (tg & 3);
        ((unsigned*)Vpk)[basei * 2 + (tg >> 2)] = vo;
    }
}

// ---------------------------------------------------------------------------
// Flash attention v6: prepacked Q/K/V, cp.async double-buffered K/V,
// Q a-fragments in registers, 1 syncthreads per k-tile.
// ---------------------------------------------------------------------------
#define UQ 68
#define QTILES (Sc / 128)   // 16
#define FP_BYTES (64 * UQ * 8)          // P buffer: 34816
#define FKV_BYTES 16384                 // one K or V tile
#define FSMEM (FP_BYTES + 4 * FKV_BYTES)   // 100352

__global__ __launch_bounds__(256, 2)
void flash_attn_kernel(const uint2* __restrict__ Qpk,
                       const uint2* __restrict__ Kpk,
                       const uint2* __restrict__ Vpk,
                       float* __restrict__ Out) {
    extern __shared__ char fsm[];
    uint2* Pp = (uint2*)fsm;                      // [64][UQ]
    unsigned smem_u;
    asm("{ .reg .u64 t; cvta.to.shared.u64 t, %1; cvt.u32.u64 %0, t; }"
        : "=r"(smem_u) : "l"(fsm));
    const unsigned sK = smem_u + FP_BYTES;
    const unsigned sV = smem_u + FP_BYTES + 2 * FKV_BYTES;

    const int tid = threadIdx.x;
    const int lane = tid & 31;
    const int w = tid >> 5;
    const int g = lane >> 2;
    const int tig = lane & 3;

    const int id = blockIdx.x;
    const int bh = id & 31;
    const int qt = (QTILES - 1) - (id >> 5);
    const int q0 = qt * 128;

    const uint2* Qt = Qpk + ((size_t)bh * 16 + qt) * 4096;
    const uint2* Kb = Kpk + (size_t)bh * 32 * 2048;
    const uint2* Vb = Vpk + (size_t)bh * 32 * 2048;

    // Q a-fragments -> registers (warp-private rows, one-time)
    uint2 qa01[8], qa23[8];
#pragma unroll
    for (int ks = 0; ks < 8; ks++) {
        qa01[ks] = Qt[(w * 8 + g) * 64 + ks * 8 + tig];
        qa23[ks] = Qt[(w * 8 + g) * 64 + ks * 8 + tig + 4];
    }

    auto issue = [&](int kt) {
        const int b = kt & 1;
        const uint2* ksrc = Kb + (size_t)kt * 2048;
        const uint2* vsrc = Vb + (size_t)kt * 2048;
#pragma unroll
        for (int i = 0; i < 4; i++) {
            int e = tid + i * 256;
            cpa16(sK + b * FKV_BYTES + e * 16, ksrc + e * 2);
        }
#pragma unroll
        for (int i = 0; i < 4; i++) {
            int e = tid + i * 256;
            cpa16(sV + b * FKV_BYTES + e * 16, vsrc + e * 2);
        }
        asm volatile("cp.async.commit_group;");
    };

    issue(0);

    float4 s[8], o[8];
#pragma unroll
    for (int t = 0; t < 8; t++) o[t] = make_float4(0.f, 0.f, 0.f, 0.f);
    float mrow0 = -INFINITY, mrow1 = -INFINITY, lrow0 = 0.f, lrow1 = 0.f;

    const int nkt = 2 * qt + 2;
    for (int kt = 0; kt < nkt; kt++) {
        const int b = kt & 1;
        asm volatile("cp.async.wait_group 0;");
        __syncthreads();                      // K[b]/V[b] visible to all
        if (kt + 1 < nkt) issue(kt + 1);      // fills b^1 during compute

        const uint2* Kp = (const uint2*)(fsm + FP_BYTES + (size_t)b * FKV_BYTES);
        const uint2* Vp = (const uint2*)(fsm + FP_BYTES + 2 * FKV_BYTES
                                             + (size_t)b * FKV_BYTES);

        // ---- S = (Q*scale) @ K^T ----
#pragma unroll
        for (int t = 0; t < 8; t++) s[t] = make_float4(0.f, 0.f, 0.f, 0.f);
#pragma unroll
        for (int ks = 0; ks < 8; ks++) {
#pragma unroll
            for (int t = 0; t < 8; t++)
                mma8(s[t], qa01[ks], qa23[ks], Kp[(ks * 8 + t) * 32 + lane]);
        }

        // Causal mask — only on the last two key tiles
        if (kt >= 2 * qt) {
            const int k0 = kt * 64;
            const int r0 = q0 + w * 16 + g;
            const int r1 = r0 + 8;
#pragma unroll
            for (int t = 0; t < 8; t++) {
                int c0 = k0 + t * 8 + 2 * tig;
                if (c0 > r0)     s[t].x = -INFINITY;
                if (c0 + 1 > r0) s[t].y = -INFINITY;
                if (c0 > r1)     s[t].z = -INFINITY;
                if (c0 + 1 > r1) s[t].w = -INFINITY;
            }
        }

        // ---- Online softmax on fragments ----
        float mx0 = -INFINITY, mx1 = -INFINITY;
#pragma unroll
        for (int t = 0; t < 8; t++) {
            mx0 = fmaxf(mx0, fmaxf(s[t].x, s[t].y));
            mx1 = fmaxf(mx1, fmaxf(s[t].z, s[t].w));
        }
        mx0 = fmaxf(mx0, __shfl_xor_sync(0xffffffffu, mx0, 1));
        mx0 = fmaxf(mx0, __shfl_xor_sync(0xffffffffu, mx0, 2));
        mx1 = fmaxf(mx1, __shfl_xor_sync(0xffffffffu, mx1, 1));
        mx1 = fmaxf(mx1, __shfl_xor_sync(0xffffffffu, mx1, 2));
        float mnew0 = fmaxf(mrow0, mx0);
        float mnew1 = fmaxf(mrow1, mx1);
        float cr0 = __expf(mrow0 - mnew0);
        float cr1 = __expf(mrow1 - mnew1);
        float sum0 = 0.f, sum1 = 0.f;
#pragma unroll
        for (int t = 0; t < 8; t++) {
            s[t].x = __expf(s[t].x - mnew0);
            s[t].y = __expf(s[t].y - mnew0);
            s[t].z = __expf(s[t].z - mnew1);
            s[t].w = __expf(s[t].w - mnew1);
            sum0 += s[t].x + s[t].y;
            sum1 += s[t].z + s[t].w;
        }
        sum0 += __shfl_xor_sync(0xffffffffu, sum0, 1);
        sum0 += __shfl_xor_sync(0xffffffffu, sum0, 2);
        sum1 += __shfl_xor_sync(0xffffffffu, sum1, 1);
        sum1 += __shfl_xor_sync(0xffffffffu, sum1, 2);
        lrow0 = lrow0 * cr0 + sum0;
        lrow1 = lrow1 * cr1 + sum1;
        mrow0 = mnew0;
        mrow1 = mnew1;
#pragma unroll
        for (int t = 0; t < 8; t++) {
            o[t].x *= cr0; o[t].y *= cr0;
            o[t].z *= cr1; o[t].w *= cr1;
        }

        // ---- Publish P (warp-private rows; no CTA barrier needed) ----
#pragma unroll
        for (int t = 0; t < 8; t++) {
            uint4 u = make_uint4(f2tf(s[t].x), f2tf(s[t].z),
                                 f2tf(s[t].y), f2tf(s[t].w));
            *(uint4*)&Pp[(w * 8 + g) * UQ + t * 8 + 2 * tig] = u;
        }
        __syncwarp();

        // ---- O += P @ V ----
#pragma unroll
        for (int js = 0; js < 8; js++) {
            uint2 a01 = Pp[(w * 8 + g) * UQ + js * 8 + tig];
            uint2 a23 = Pp[(w * 8 + g) * UQ + js * 8 + tig + 4];
#pragma unroll
            for (int t = 0; t < 8; t++)
                mma8(o[t], a01, a23, Vp[(js * 8 + t) * 32 + lane]);
        }
    }

    // Normalize and write out as [B,S,H*DK]
    const int b = bh >> 4;
    const int h = bh & 15;
    const float inv0 = 1.0f / lrow0;
    const float inv1 = 1.0f / lrow1;
    const size_t row0 = (size_t)(b * Sc + q0 + w * 16 + g) * Dc + h * DKc;
    const size_t row1 = row0 + 8 * Dc;
#pragma unroll
    for (int t = 0; t < 8; t++) {
        *(float2*)&Out[row0 + t * 8 + 2 * tig] =
            make_float2(o[t].x * inv0, o[t].y * inv0);
        *(float2*)&Out[row1 + t * 8 + 2 * tig] =
            make_float2(o[t].z * inv1, o[t].w * inv1);
    }
}

// ---------------------------------------------------------------------------
extern "C" void kernel_launch(void* const* d_in, const int* in_sizes, int n_in,
                              void* d_out, int out_size) {
    const float* x    = (const float*)d_in[0];   // [B,S,D]
    const float* Wqkv = (const float*)d_in[1];   // [D, 3D]
    const float* Wo   = (const float*)d_in[2];   // [D, D]
    float* out = (float*)d_out;

    float *qkv, *attn;
    uint2 *apkx, *bpkq, *apka, *bpkw, *qpk, *kpk, *vpk;
    cudaGetSymbolAddress((void**)&qkv,  g_qkv);
    cudaGetSymbolAddress((void**)&attn, g_attn);
    cudaGetSymbolAddress((void**)&apkx, g_apk_x);
    cudaGetSymbolAddress((void**)&bpkq, g_bpk_qkv);
    cudaGetSymbolAddress((void**)&apka, g_apk_attn);
    cudaGetSymbolAddress((void**)&bpkw, g_bpk_wo);
    cudaGetSymbolAddress((void**)&qpk,  g_qpk);
    cudaGetSymbolAddress((void**)&kpk,  g_kpk);
    cudaGetSymbolAddress((void**)&vpk,  g_vpk);

    // 0. RoPE tables
    rope_table_kernel<<<(Sc * 32) / 256, 256>>>();

    // 1. QKV projection (prepack + cp.async tf32 GEMM)
    prepackA_kernel<<<(BSc * Dc / 2) / 256, 256>>>(x, apkx, Dc);
    prepackB_kernel<<<(Dc * 3 * Dc / 2) / 256, 256>>>(Wqkv, bpkq, 3 * Dc);
    cudaFuncSetAttribute(tgemm_packed,
                         cudaFuncAttributeMaxDynamicSharedMemorySize, SMEM_TOTAL);
    tgemm_packed<<<dim3(3 * Dc / 128, BSc / 128), 256, SMEM_TOTAL>>>(
        apkx, bpkq, qkv, BSc, 3 * Dc);

    // 2. RoPE + fragment-pack Q/K/V
    rope_pack_kernel<<<(Bc * Sc * Hc * DKc) / 256, 256>>>(qkv, qpk, kpk, vpk);

    // 3. Causal flash attention (prepacked, cp.async double-buffered)
    cudaFuncSetAttribute(flash_attn_kernel,
                         cudaFuncAttributeMaxDynamicSharedMemorySize, FSMEM);
    flash_attn_kernel<<<32 * QTILES, 256, FSMEM>>>(qpk, kpk, vpk, attn);

    // 4. Output projection (prepack + cp.async tf32 GEMM)
    prepackA_kernel<<<(BSc * Dc / 2) / 256, 256>>>(attn, apka, Dc);
    prepackB_kernel<<<(Dc * Dc / 2) / 256, 256>>>(Wo, bpkw, Dc);
    tgemm_packed<<<dim3(Dc / 128, BSc / 128), 256, SMEM_TOTAL>>>(
        apka, bpkw, out, BSc, Dc);
}

// round 14
// speedup vs baseline: 1.0020x; 1.0020x over previous
#include <cuda_runtime.h>
#include <math.h>

#define Bc 2
#define Sc 2048
#define Dc 1024
#define Hc 16
#define DKc 64
#define BSc (Bc*Sc)   // 4096

// Scratch (no allocations allowed)
__device__ float g_qkv[(size_t)BSc * 3 * Dc];      // [B,S,3,H,DK]
__device__ float g_attn[(size_t)BSc * Dc];         // [B,S,D]
__device__ float g_ctab[Sc * 32];                  // RoPE cos table
__device__ float g_stab[Sc * 32];                  // RoPE sin table

// Packed tf32 tile buffers for the GEMMs (tile-major, fragment order)
__device__ uint2 g_apk_x[(size_t)BSc * Dc / 2];
__device__ uint2 g_bpk_qkv[(size_t)Dc * 3 * Dc / 2];
__device__ uint2 g_apk_attn[(size_t)BSc * Dc / 2];
__device__ uint2 g_bpk_wo[(size_t)Dc * Dc / 2];

// Packed tf32 Q/K/V for flash (written by rope_pack)
__device__ uint2 g_qpk[(size_t)32 * 16 * 4096];    // [bh][qt128] a-frag pairs
__device__ uint2 g_kpk[(size_t)32 * 32 * 2048];    // [bh][kt64]  b-frag pairs
__device__ uint2 g_vpk[(size_t)32 * 32 * 2048];    // [bh][kt64]  b-frag pairs

__device__ __forceinline__ unsigned f2tf(float x) {
    unsigned r;
    asm("cvt.rna.tf32.f32 %0, %1;" : "=r"(r) : "f"(x));
    return r;
}

__device__ __forceinline__ void mma8(float4& d, uint2 a01, uint2 a23, uint2 b) {
    asm volatile(
        "mma.sync.aligned.m16n8k8.row.col.f32.tf32.tf32.f32 "
        "{%0,%1,%2,%3}, {%4,%5,%6,%7}, {%8,%9}, {%0,%1,%2,%3};\n"
        : "+f"(d.x), "+f"(d.y), "+f"(d.z), "+f"(d.w)
        : "r"(a01.x), "r"(a01.y), "r"(a23.x), "r"(a23.y), "r"(b.x), "r"(b.y));
}

__device__ __forceinline__ void cpa16(unsigned dst, const void* src) {
    asm volatile("cp.async.cg.shared.global [%0], [%1], 16;"
                 :: "r"(dst), "l"(src));
}

// ---------------------------------------------------------------------------
// Pre-pack A[M,K=1024] -> tile-major a-fragment pairs (unchanged from R10)
// ---------------------------------------------------------------------------
__global__ void prepackA_kernel(const float* __restrict__ A,
                                uint2* __restrict__ out, int K) {
    int idx = blockIdx.x * blockDim.x + threadIdx.x;
    int k = idx & 31;
    int rg = (idx >> 5) & 63;
    int ck = idx >> 11;
    int kt = ck & 31;
    int mt = ck >> 5;
    int r = mt * 128 + ((rg >> 3) << 4) + (rg & 7);
    int col = kt * 32 + k;
    out[idx] = make_uint2(f2tf(A[(size_t)r * K + col]),
                          f2tf(A[(size_t)(r + 8) * K + col]));
}

// ---------------------------------------------------------------------------
// Pre-pack B[K=1024,N] -> tile-major b-fragment pairs (unchanged from R10)
// ---------------------------------------------------------------------------
__global__ void prepackB_kernel(const float* __restrict__ B,
                                uint2* __restrict__ out, int N) {
    int idx = blockIdx.x * blockDim.x + threadIdx.x;
    int pos = idx & 2047;
    int ck = idx >> 11;
    int kt = ck & 31;
    int nt = ck >> 5;
    int tg = pos & 3;
    int col = (((pos >> 5) & 15) << 3) + ((pos >> 2) & 7);
    int ks = pos >> 9;
    int row = kt * 32 + ks * 8 + tg;
    int c = nt * 128 + col;
    out[idx] = make_uint2(f2tf(B[(size_t)row * N + c]),
                          f2tf(B[(size_t)(row + 4) * N + c]));
}

// ---------------------------------------------------------------------------
// tf32 GEMM on prepacked tiles, cp.async double-buffered (unchanged from R10)
// ---------------------------------------------------------------------------
#define AS 36
#define BUFA_BYTES (64 * AS * 8)
#define BUFB_BYTES (64 * 32 * 8)
#define SMEM_TOTAL (2 * (BUFA_BYTES + BUFB_BYTES))   // 69632

__global__ __launch_bounds__(256, 2)
void tgemm_packed(const uint2* __restrict__ Apk,
                  const uint2* __restrict__ Bpk,
                  float* __restrict__ C, int M, int N) {
    extern __shared__ char smraw[];
    unsigned smem_u;
    asm("{ .reg .u64 t; cvta.to.shared.u64 t, %1; cvt.u32.u64 %0, t; }"
        : "=r"(smem_u) : "l"(smraw));
    const unsigned sA0 = smem_u;
    const unsigned sB0 = smem_u + 2 * BUFA_BYTES;

    const int tid = threadIdx.x;
    const int lane = tid & 31;
    const int w = tid >> 5;
    const int g = lane >> 2;
    const int tig = lane & 3;
    const int wm = w >> 2;
    const int wn = w & 3;
    const int mt_blk = blockIdx.y;
    const int nt_blk = blockIdx.x;

    const uint2* Abase = Apk + (size_t)mt_blk * 32 * 2048;
    const uint2* Bbase = Bpk + (size_t)nt_blk * 32 * 2048;

    auto issue = [&](int kt, int b) {
        const uint2* at = Abase + (size_t)kt * 2048;
        const uint2* bt = Bbase + (size_t)kt * 2048;
        unsigned dA = sA0 + b * BUFA_BYTES;
        unsigned dB = sB0 + b * BUFB_BYTES;
#pragma unroll
        for (int i = 0; i < 4; i++) {
            int e = tid + i * 256;
            int rg = e >> 4, c = e & 15;
            cpa16(dA + rg * (AS * 8) + c * 16, at + e * 2);
        }
#pragma unroll
        for (int i = 0; i < 4; i++) {
            int e = tid + i * 256;
            cpa16(dB + e * 16, bt + e * 2);
        }
        asm volatile("cp.async.commit_group;");
    };

    issue(0, 0);

    float4 acc[4][4];
#pragma unroll
    for (int i = 0; i < 4; i++)
#pragma unroll
        for (int j = 0; j < 4; j++) acc[i][j] = make_float4(0.f, 0.f, 0.f, 0.f);

    for (int kt = 0; kt < 32; kt++) {
        const int b = kt & 1;
        if (kt + 1 < 32) {
            issue(kt + 1, b ^ 1);
            asm volatile("cp.async.wait_group 1;");
        } else {
            asm volatile("cp.async.wait_group 0;");
        }
        __syncthreads();

        const uint2* Ap = (const uint2*)(smraw + (size_t)b * BUFA_BYTES);
        const uint2* Bp = (const uint2*)(smraw + 2 * BUFA_BYTES
                                               + (size_t)b * BUFB_BYTES);
#pragma unroll
        for (int ks = 0; ks < 4; ks++) {
            uint2 bfr[4];
#pragma unroll
            for (int nt = 0; nt < 4; nt++)
                bfr[nt] = Bp[(ks * 16 + wn * 4 + nt) * 32 + lane];
#pragma unroll
            for (int mt = 0; mt < 4; mt++) {
                uint2 a01 = Ap[(wm * 32 + mt * 8 + g) * AS + ks * 8 + tig];
                uint2 a23 = Ap[(wm * 32 + mt * 8 + g) * AS + ks * 8 + tig + 4];
#pragma unroll
                for (int nt = 0; nt < 4; nt++)
                    mma8(acc[mt][nt], a01, a23, bfr[nt]);
            }
        }
        __syncthreads();
    }

    const int m0 = mt_blk << 7;
    const int n0 = nt_blk << 7;
#pragma unroll
    for (int mt = 0; mt < 4; mt++) {
        int row = m0 + wm * 64 + mt * 16 + g;
#pragma unroll
        for (int nt = 0; nt < 4; nt++) {
            int col = n0 + wn * 32 + nt * 8 + 2 * tig;
            *(float2*)&C[(size_t)row * N + col] =
                make_float2(acc[mt][nt].x, acc[mt][nt].y);
            *(float2*)&C[(size_t)(row + 8) * N + col] =
                make_float2(acc[mt][nt].z, acc[mt][nt].w);
        }
    }
}

// ---------------------------------------------------------------------------
// RoPE table precompute (unchanged)
// ---------------------------------------------------------------------------
__global__ void rope_table_kernel() {
    int idx = blockIdx.x * blockDim.x + threadIdx.x;
    int d2 = idx & 31;
    int s = idx >> 5;
    float invf = 1.0f / powf(10000.0f, (float)d2 * (1.0f / 32.0f));
    float ang = (float)s * invf;
    float sn, c;
    sincosf(ang, &sn, &c);
    g_ctab[idx] = c;
    g_stab[idx] = sn;
}

// ---------------------------------------------------------------------------
// RoPE + pack: applies rotary, then writes Q/K/V directly in the tf32
// fragment-packed tile layouts flash consumes. Same arithmetic as before
// (fp32 rope -> [scale] -> cvt.rna.tf32), just relocated.
// ---------------------------------------------------------------------------
__global__ void rope_pack_kernel(const float* __restrict__ qkv,
                                 uint2* __restrict__ Qpk,
                                 uint2* __restrict__ Kpk,
                                 uint2* __restrict__ Vpk) {
    int idx = blockIdx.x * blockDim.x + threadIdx.x;  // [b][s][h][d]
    int d = idx & 63;
    int h = (idx >> 6) & (Hc - 1);
    int s = (idx >> 10) & (Sc - 1);
    int b = idx >> 21;

    const float* base = qkv + (size_t)(b * Sc + s) * 3 * Dc + h * DKc;
    float qv = base[d];
    float kv = base[Dc + d];
    float vv = base[2 * Dc + d];

    int d2 = d & 31;
    float c = g_ctab[s * 32 + d2];
    float sn = g_stab[s * 32 + d2];

    int dp = d ^ 32;
    float qp = base[dp];
    float kp = base[Dc + dp];
    float sgn = (d < 32) ? -1.0f : 1.0f;

    unsigned qo = f2tf((qv * c + sgn * qp * sn) * 0.125f);  // fold 1/sqrt(dk)
    unsigned ko = f2tf(kv * c + sgn * kp * sn);
    unsigned vo = f2tf(vv);

    const int bh = b * Hc + h;

    // Q: a-frag pairs, tile (bh, s>>7), pos rg*64+d, half = (r&15)>=8
    {
        int qt = s >> 7, r = s & 127;
        int grp = r >> 4, wi = r & 15;
        size_t basei = ((size_t)bh * 16 + qt) * 4096 + (grp * 8 + (wi & 7)) * 64 + d;
        ((unsigned*)Qpk)[basei * 2 + (wi >> 3)] = qo;
    }
    // K: b-frag pairs over d, tile (bh, s>>6)
    {
        int kt = s >> 6, key = s & 63;
        int ks = d >> 3, j = d & 7;
        size_t basei = ((size_t)bh * 32 + kt) * 2048
                     + (ks * 8 + (key >> 3)) * 32 + (key & 7) * 4 + (j & 3);
        ((unsigned*)Kpk)[basei * 2 + (j >> 2)] = ko;
    }
    // V: b-frag pairs over rows, tile (bh, s>>6)
    {
        int kt = s >> 6, rk = s & 63;
        int js = rk >> 3, tg = rk & 7;
        size_t basei = ((size_t)bh * 32 + kt) * 2048
                     + (js * 8 + (d >> 3)) * 32 + (d & 7) * 4 + (tg & 3);
        ((unsigned*)Vpk)[basei * 2 + (tg >> 2)] = vo;
    }
}

// ---------------------------------------------------------------------------
// Flash attention v6: prepacked Q/K/V, cp.async double-buffered K/V,
// Q a-fragments in registers, 1 syncthreads per k-tile.
// ---------------------------------------------------------------------------
#define UQ 68
#define QTILES (Sc / 128)   // 16
#define FP_BYTES (64 * UQ * 8)          // P buffer: 34816
#define FKV_BYTES 16384                 // one K or V tile
#define FSMEM (FP_BYTES + 4 * FKV_BYTES)   // 100352

__global__ __launch_bounds__(256, 2)
void flash_attn_kernel(const uint2* __restrict__ Qpk,
                       const uint2* __restrict__ Kpk,
                       const uint2* __restrict__ Vpk,
                       float* __restrict__ Out) {
    extern __shared__ char fsm[];
    uint2* Pp = (uint2*)fsm;                      // [64][UQ]
    unsigned smem_u;
    asm("{ .reg .u64 t; cvta.to.shared.u64 t, %1; cvt.u32.u64 %0, t; }"
        : "=r"(smem_u) : "l"(fsm));
    const unsigned sK = smem_u + FP_BYTES;
    const unsigned sV = smem_u + FP_BYTES + 2 * FKV_BYTES;

    const int tid = threadIdx.x;
    const int lane = tid & 31;
    const int w = tid >> 5;
    const int g = lane >> 2;
    const int tig = lane & 3;

    const int id = blockIdx.x;
    const int bh = id & 31;
    const int qt = (QTILES - 1) - (id >> 5);
    const int q0 = qt * 128;

    const uint2* Qt = Qpk + ((size_t)bh * 16 + qt) * 4096;
    const uint2* Kb = Kpk + (size_t)bh * 32 * 2048;
    const uint2* Vb = Vpk + (size_t)bh * 32 * 2048;

    // Q a-fragments -> registers (warp-private rows, one-time)
    uint2 qa01[8], qa23[8];
#pragma unroll
    for (int ks = 0; ks < 8; ks++) {
        qa01[ks] = Qt[(w * 8 + g) * 64 + ks * 8 + tig];
        qa23[ks] = Qt[(w * 8 + g) * 64 + ks * 8 + tig + 4];
    }

    auto issue = [&](int kt) {
        const int b = kt & 1;
        const uint2* ksrc = Kb + (size_t)kt * 2048;
        const uint2* vsrc = Vb + (size_t)kt * 2048;
#pragma unroll
        for (int i = 0; i < 4; i++) {
            int e = tid + i * 256;
            cpa16(sK + b * FKV_BYTES + e * 16, ksrc + e * 2);
        }
#pragma unroll
        for (int i = 0; i < 4; i++) {
            int e = tid + i * 256;
            cpa16(sV + b * FKV_BYTES + e * 16, vsrc + e * 2);
        }
        asm volatile("cp.async.commit_group;");
    };

    issue(0);

    float4 s[8], o[8];
#pragma unroll
    for (int t = 0; t < 8; t++) o[t] = make_float4(0.f, 0.f, 0.f, 0.f);
    float mrow0 = -INFINITY, mrow1 = -INFINITY, lrow0 = 0.f, lrow1 = 0.f;

    const int nkt = 2 * qt + 2;
    for (int kt = 0; kt < nkt; kt++) {
        const int b = kt & 1;
        asm volatile("cp.async.wait_group 0;");
        __syncthreads();                      // K[b]/V[b] visible to all
        if (kt + 1 < nkt) issue(kt + 1);      // fills b^1 during compute

        const uint2* Kp = (const uint2*)(fsm + FP_BYTES + (size_t)b * FKV_BYTES);
        const uint2* Vp = (const uint2*)(fsm + FP_BYTES + 2 * FKV_BYTES
                                             + (size_t)b * FKV_BYTES);

        // ---- S = (Q*scale) @ K^T ----
#pragma unroll
        for (int t = 0; t < 8; t++) s[t] = make_float4(0.f, 0.f, 0.f, 0.f);
#pragma unroll
        for (int ks = 0; ks < 8; ks++) {
#pragma unroll
            for (int t = 0; t < 8; t++)
                mma8(s[t], qa01[ks], qa23[ks], Kp[(ks * 8 + t) * 32 + lane]);
        }

        // Causal mask — only on the last two key tiles
        if (kt >= 2 * qt) {
            const int k0 = kt * 64;
            const int r0 = q0 + w * 16 + g;
            const int r1 = r0 + 8;
#pragma unroll
            for (int t = 0; t < 8; t++) {
                int c0 = k0 + t * 8 + 2 * tig;
                if (c0 > r0)     s[t].x = -INFINITY;
                if (c0 + 1 > r0) s[t].y = -INFINITY;
                if (c0 > r1)     s[t].z = -INFINITY;
                if (c0 + 1 > r1) s[t].w = -INFINITY;
            }
        }

        // ---- Online softmax on fragments ----
        float mx0 = -INFINITY, mx1 = -INFINITY;
#pragma unroll
        for (int t = 0; t < 8; t++) {
            mx0 = fmaxf(mx0, fmaxf(s[t].x, s[t].y));
            mx1 = fmaxf(mx1, fmaxf(s[t].z, s[t].w));
        }
        mx0 = fmaxf(mx0, __shfl_xor_sync(0xffffffffu, mx0, 1));
        mx0 = fmaxf(mx0, __shfl_xor_sync(0xffffffffu, mx0, 2));
        mx1 = fmaxf(mx1, __shfl_xor_sync(0xffffffffu, mx1, 1));
        mx1 = fmaxf(mx1, __shfl_xor_sync(0xffffffffu, mx1, 2));
        float mnew0 = fmaxf(mrow0, mx0);
        float mnew1 = fmaxf(mrow1, mx1);
        float cr0 = __expf(mrow0 - mnew0);
        float cr1 = __expf(mrow1 - mnew1);
        float sum0 = 0.f, sum1 = 0.f;
#pragma unroll
        for (int t = 0; t < 8; t++) {
            s[t].x = __expf(s[t].x - mnew0);
            s[t].y = __expf(s[t].y - mnew0);
            s[t].z = __expf(s[t].z - mnew1);
            s[t].w = __expf(s[t].w - mnew1);
            sum0 += s[t].x + s[t].y;
            sum1 += s[t].z + s[t].w;
        }
        sum0 += __shfl_xor_sync(0xffffffffu, sum0, 1);
        sum0 += __shfl_xor_sync(0xffffffffu, sum0, 2);
        sum1 += __shfl_xor_sync(0xffffffffu, sum1, 1);
        sum1 += __shfl_xor_sync(0xffffffffu, sum1, 2);
        lrow0 = lrow0 * cr0 + sum0;
        lrow1 = lrow1 * cr1 + sum1;
        mrow0 = mnew0;
        mrow1 = mnew1;
#pragma unroll
        for (int t = 0; t < 8; t++) {
            o[t].x *= cr0; o[t].y *= cr0;
            o[t].z *= cr1; o[t].w *= cr1;
        }

        // ---- Publish P (warp-private rows; no CTA barrier needed) ----
#pragma unroll
        for (int t = 0; t < 8; t++) {
            uint4 u = make_uint4(f2tf(s[t].x), f2tf(s[t].z),
                                 f2tf(s[t].y), f2tf(s[t].w));
            *(uint4*)&Pp[(w * 8 + g) * UQ + t * 8 + 2 * tig] = u;
        }
        __syncwarp();

        // ---- O += P @ V ----
#pragma unroll
        for (int js = 0; js < 8; js++) {
            uint2 a01 = Pp[(w * 8 + g) * UQ + js * 8 + tig];
            uint2 a23 = Pp[(w * 8 + g) * UQ + js * 8 + tig + 4];
#pragma unroll
            for (int t = 0; t < 8; t++)
                mma8(o[t], a01, a23, Vp[(js * 8 + t) * 32 + lane]);
        }
    }

    // Normalize and write out as [B,S,H*DK]
    const int b = bh >> 4;
    const int h = bh & 15;
    const float inv0 = 1.0f / lrow0;
    const float inv1 = 1.0f / lrow1;
    const size_t row0 = (size_t)(b * Sc + q0 + w * 16 + g) * Dc + h * DKc;
    const size_t row1 = row0 + 8 * Dc;
#pragma unroll
    for (int t = 0; t < 8; t++) {
        *(float2*)&Out[row0 + t * 8 + 2 * tig] =
            make_float2(o[t].x * inv0, o[t].y * inv0);
        *(float2*)&Out[row1 + t * 8 + 2 * tig] =
            make_float2(o[t].z * inv1, o[t].w * inv1);
    }
}

// ---------------------------------------------------------------------------
extern "C" void kernel_launch(void* const* d_in, const int* in_sizes, int n_in,
                              void* d_out, int out_size) {
    const float* x    = (const float*)d_in[0];   // [B,S,D]
    const float* Wqkv = (const float*)d_in[1];   // [D, 3D]
    const float* Wo   = (const float*)d_in[2];   // [D, D]
    float* out = (float*)d_out;

    float *qkv, *attn;
    uint2 *apkx, *bpkq, *apka, *bpkw, *qpk, *kpk, *vpk;
    cudaGetSymbolAddress((void**)&qkv,  g_qkv);
    cudaGetSymbolAddress((void**)&attn, g_attn);
    cudaGetSymbolAddress((void**)&apkx, g_apk_x);
    cudaGetSymbolAddress((void**)&bpkq, g_bpk_qkv);
    cudaGetSymbolAddress((void**)&apka, g_apk_attn);
    cudaGetSymbolAddress((void**)&bpkw, g_bpk_wo);
    cudaGetSymbolAddress((void**)&qpk,  g_qpk);
    cudaGetSymbolAddress((void**)&kpk,  g_kpk);
    cudaGetSymbolAddress((void**)&vpk,  g_vpk);

    // 0. RoPE tables
    rope_table_kernel<<<(Sc * 32) / 256, 256>>>();

    // 1. QKV projection (prepack + cp.async tf32 GEMM)
    prepackA_kernel<<<(BSc * Dc / 2) / 256, 256>>>(x, apkx, Dc);
    prepackB_kernel<<<(Dc * 3 * Dc / 2) / 256, 256>>>(Wqkv, bpkq, 3 * Dc);
    cudaFuncSetAttribute(tgemm_packed,
                         cudaFuncAttributeMaxDynamicSharedMemorySize, SMEM_TOTAL);
    tgemm_packed<<<dim3(3 * Dc / 128, BSc / 128), 256, SMEM_TOTAL>>>(
        apkx, bpkq, qkv, BSc, 3 * Dc);

    // 2. RoPE + fragment-pack Q/K/V
    rope_pack_kernel<<<(Bc * Sc * Hc * DKc) / 256, 256>>>(qkv, qpk, kpk, vpk);

    // 3. Causal flash attention (prepacked, cp.async double-buffered)
    cudaFuncSetAttribute(flash_attn_kernel,
                         cudaFuncAttributeMaxDynamicSharedMemorySize, FSMEM);
    flash_attn_kernel<<<32 * QTILES, 256, FSMEM>>>(qpk, kpk, vpk, attn);

    // 4. Output projection (prepack + cp.async tf32 GEMM)
    prepackA_kernel<<<(BSc * Dc / 2) / 256, 256>>>(attn, apka, Dc);
    prepackB_kernel<<<(Dc * Dc / 2) / 256, 256>>>(Wo, bpkw, Dc);
    tgemm_packed<<<dim3(Dc / 128, BSc / 128), 256, SMEM_TOTAL>>>(
        apka, bpkw, out, BSc, Dc);
}